// round 12
// baseline (speedup 1.0000x reference)
#include <cuda_runtime.h>
#include <cuda_bf16.h>

// Problem constants
#define N1M1 4096          // row width of b / y
#define ROWS 8191          // n2 - 1 rows contribute
#define THREADS 256
#define GBLOCKS 1184       // 148 SMs x 8 CTAs -> single wave (32 regs -> occ 8)

__device__ float        g_partials[GBLOCKS];
__device__ unsigned int g_count = 0;

__global__ __launch_bounds__(THREADS)
void rosen_fused_kernel(const float* __restrict__ x,
                        const float* __restrict__ a,
                        const float* __restrict__ b,
                        const float* __restrict__ mu,
                        float* __restrict__ out)
{
    const int tid  = threadIdx.x;
    const int lane = tid & 31;
    const int wid  = tid >> 5;
    // Warp-contiguous mapping: warp w owns columns [w*512, w*512+512).
    // Load s covers columns w*512 + s*128 + lane*4 .. +3  -> the warp's 4 x-loads
    // (and 4 b-loads) form one sequential 2KB burst each (DRAM row-buffer friendly).
    const int wbase = (wid << 9) + (lane << 2);

    float sum = 0.0f;

    for (int i = blockIdx.x; i < ROWS; i += GBLOCKS) {
        const long  base = (long)i * N1M1;
        const float* xp  = x + base + wbase;
        const float* bp  = b + base + wbase;

        // 8 front-batched, warp-coalesced LDG.128; per-warp sequential 2KB bursts.
        float4 xv[4], bv[4];
        #pragma unroll
        for (int s = 0; s < 4; s++) {
            xv[s] = *reinterpret_cast<const float4*>(xp + s * 128);
            bv[s] = *reinterpret_cast<const float4*>(bp + s * 128);
        }
        // Single boundary scalar per warp (lane 31, after segment 3):
        // x[base + w*512 + 512]; for wid 7 this is x[base+4096] (always in bounds).
        const float nxt  = (lane == 31) ? xp[3 * 128 + 4] : 0.0f;
        // Roll wrap (tid 0 only): y_prev[i,0] = x[base + 4096].
        const float xwrp = (tid == 0) ? x[base + N1M1] : 0.0f;

        // cur[3] per segment: next lane's xv[s].x; lane 31 takes lane 0 of
        // segment s+1 (same warp, shuffle) or the scalar for s==3.
        float c3[4];
        #pragma unroll
        for (int s = 0; s < 4; s++) {
            const float nb = __shfl_sync(0xFFFFFFFFu, xv[s].x, (lane + 1) & 31);
            float wrapv;
            if (s < 3) wrapv = __shfl_sync(0xFFFFFFFFu, xv[s + 1].x, 0);
            else       wrapv = nxt;
            c3[s] = (lane == 31) ? wrapv : nb;
        }

        #pragma unroll
        for (int s = 0; s < 4; s++) {
            float p0 = xv[s].x;
            if (s == 0 && tid == 0) p0 = xwrp;           // roll wrap at column 0
            float w2 = bv[s].z, w3 = bv[s].w;
            if (s == 3 && tid == THREADS - 1) {          // cols 4094,4095 excluded
                w2 = 0.0f; w3 = 0.0f;
            }
            float d;
            d = xv[s].y - p0      * p0;       sum += bv[s].x * d * d;
            d = xv[s].z - xv[s].y * xv[s].y;  sum += bv[s].y * d * d;
            d = xv[s].w - xv[s].z * xv[s].z;  sum += w2      * d * d;
            d = c3[s]   - xv[s].w * xv[s].w;  sum += w3      * d * d;
        }
    }

    // Warp tree reduce
    #pragma unroll
    for (int off = 16; off > 0; off >>= 1)
        sum += __shfl_xor_sync(0xFFFFFFFFu, sum, off);

    // Block reduce across 8 warps
    __shared__ float s_red[THREADS / 32];
    __shared__ bool  s_last;
    if (lane == 0) s_red[wid] = sum;
    __syncthreads();
    if (wid == 0) {
        float v = (lane < THREADS / 32) ? s_red[lane] : 0.0f;
        #pragma unroll
        for (int off = 4; off > 0; off >>= 1)
            v += __shfl_xor_sync(0xFFFFFFFFu, v, off);
        if (lane == 0) {
            g_partials[blockIdx.x] = v;
            // acq_rel atomic: release orders the partial store without the
            // CCTL.IVALL L1-flush of __threadfence; acquire covers last block's reads.
            unsigned int prev;
            asm volatile("atom.acq_rel.gpu.global.add.u32 %0, [%1], %2;"
                         : "=r"(prev)
                         : "l"(&g_count), "r"(1u)
                         : "memory");
            s_last = (prev == GBLOCKS - 1);
        }
    }
    __syncthreads();

    // Last-arriving block: deterministic final reduction (fixed order).
    if (s_last) {
        float v = 0.0f;
        #pragma unroll
        for (int t = tid; t < GBLOCKS; t += THREADS)   // 5 rounds
            v += __ldcg(&g_partials[t]);               // L2-direct, no stale L1

        #pragma unroll
        for (int off = 16; off > 0; off >>= 1)
            v += __shfl_xor_sync(0xFFFFFFFFu, v, off);

        if (lane == 0) s_red[wid] = v;
        __syncthreads();
        if (wid == 0) {
            float w = (lane < THREADS / 32) ? s_red[lane] : 0.0f;
            #pragma unroll
            for (int off = 4; off > 0; off >>= 1)
                w += __shfl_xor_sync(0xFFFFFFFFu, w, off);
            if (lane == 0) {
                const float dd = x[0] - mu[0];
                out[0] = -a[0] * dd * dd - w;
                g_count = 0;   // reset for next graph replay
            }
        }
    }
}

extern "C" void kernel_launch(void* const* d_in, const int* in_sizes, int n_in,
                              void* d_out, int out_size)
{
    const float* x  = (const float*)d_in[0];
    const float* a  = (const float*)d_in[1];
    const float* b  = (const float*)d_in[2];
    const float* mu = (const float*)d_in[3];
    float* out = (float*)d_out;

    rosen_fused_kernel<<<GBLOCKS, THREADS>>>(x, a, b, mu, out);
}

// round 13
// speedup vs baseline: 1.0537x; 1.0537x over previous
#include <cuda_runtime.h>
#include <cuda_bf16.h>

// Problem constants
#define N1M1 4096          // row width of b / y
#define ROWS 8191          // n2 - 1 rows contribute
#define THREADS 256
#define GBLOCKS 740        // 148 SMs x 5 CTAs (48 regs -> occ 5) -> single wave

__device__ float        g_partials[GBLOCKS];
__device__ unsigned int g_count = 0;

__global__ __launch_bounds__(THREADS)
void rosen_fused_kernel(const float* __restrict__ x,
                        const float* __restrict__ a,
                        const float* __restrict__ b,
                        const float* __restrict__ mu,
                        float* __restrict__ out)
{
    const int tid  = threadIdx.x;
    const int lane = tid & 31;
    const int wid  = tid >> 5;
    // Warp-contiguous mapping: warp w owns columns [w*512, w*512+512).
    // The warp's 4 x-loads (and 4 b-loads) form one sequential 2KB burst each
    // (DRAM row-buffer friendly; measured DRAM 77.1% -> 79.6%).
    const int wbase = (wid << 9) + (lane << 2);

    float sum = 0.0f;

    for (int i = blockIdx.x; i < ROWS; i += GBLOCKS) {
        const long  base = (long)i * N1M1;
        const float* xp  = x + base + wbase;
        const float* bp  = b + base + wbase;

        // 8 front-batched, warp-coalesced LDG.128.
        float4 xv[4], bv[4];
        #pragma unroll
        for (int s = 0; s < 4; s++) {
            xv[s] = *reinterpret_cast<const float4*>(xp + s * 128);
            bv[s] = *reinterpret_cast<const float4*>(bp + s * 128);
        }
        // Single boundary scalar per warp (lane 31, after segment 3):
        // x[base + w*512 + 512]; for wid 7 this is x[base+4096] (in bounds).
        const float nxt  = (lane == 31) ? xp[3 * 128 + 4] : 0.0f;
        // Roll wrap (tid 0 only): y_prev[i,0] = x[base + 4096].
        const float xwrp = (tid == 0) ? x[base + N1M1] : 0.0f;

        // cur[3] per segment: next lane's xv[s].x; lane 31 takes lane 0 of
        // segment s+1 (same warp, shuffle) or the scalar for s==3.
        float c3[4];
        #pragma unroll
        for (int s = 0; s < 4; s++) {
            const float nb = __shfl_sync(0xFFFFFFFFu, xv[s].x, (lane + 1) & 31);
            float wrapv;
            if (s < 3) wrapv = __shfl_sync(0xFFFFFFFFu, xv[s + 1].x, 0);
            else       wrapv = nxt;
            c3[s] = (lane == 31) ? wrapv : nb;
        }

        #pragma unroll
        for (int s = 0; s < 4; s++) {
            float p0 = xv[s].x;
            if (s == 0 && tid == 0) p0 = xwrp;           // roll wrap at column 0
            float w2 = bv[s].z, w3 = bv[s].w;
            if (s == 3 && tid == THREADS - 1) {          // cols 4094,4095 excluded
                w2 = 0.0f; w3 = 0.0f;
            }
            float d;
            d = xv[s].y - p0      * p0;       sum += bv[s].x * d * d;
            d = xv[s].z - xv[s].y * xv[s].y;  sum += bv[s].y * d * d;
            d = xv[s].w - xv[s].z * xv[s].z;  sum += w2      * d * d;
            d = c3[s]   - xv[s].w * xv[s].w;  sum += w3      * d * d;
        }
    }

    // Warp tree reduce
    #pragma unroll
    for (int off = 16; off > 0; off >>= 1)
        sum += __shfl_xor_sync(0xFFFFFFFFu, sum, off);

    // Block reduce across 8 warps
    __shared__ float s_red[THREADS / 32];
    __shared__ bool  s_last;
    if (lane == 0) s_red[wid] = sum;
    __syncthreads();
    if (wid == 0) {
        float v = (lane < THREADS / 32) ? s_red[lane] : 0.0f;
        #pragma unroll
        for (int off = 4; off > 0; off >>= 1)
            v += __shfl_xor_sync(0xFFFFFFFFu, v, off);
        if (lane == 0) {
            g_partials[blockIdx.x] = v;
            // acq_rel atomic: release orders the partial store without the
            // CCTL.IVALL L1-flush of __threadfence; acquire covers last block's reads.
            unsigned int prev;
            asm volatile("atom.acq_rel.gpu.global.add.u32 %0, [%1], %2;"
                         : "=r"(prev)
                         : "l"(&g_count), "r"(1u)
                         : "memory");
            s_last = (prev == GBLOCKS - 1);
        }
    }
    __syncthreads();

    // Last-arriving block: deterministic final reduction (fixed order).
    if (s_last) {
        float v = 0.0f;
        #pragma unroll
        for (int t = tid; t < GBLOCKS; t += THREADS)   // 3 rounds (740/256)
            v += __ldcg(&g_partials[t]);               // L2-direct, no stale L1

        #pragma unroll
        for (int off = 16; off > 0; off >>= 1)
            v += __shfl_xor_sync(0xFFFFFFFFu, v, off);

        if (lane == 0) s_red[wid] = v;
        __syncthreads();
        if (wid == 0) {
            float w = (lane < THREADS / 32) ? s_red[lane] : 0.0f;
            #pragma unroll
            for (int off = 4; off > 0; off >>= 1)
                w += __shfl_xor_sync(0xFFFFFFFFu, w, off);
            if (lane == 0) {
                const float dd = x[0] - mu[0];
                out[0] = -a[0] * dd * dd - w;
                g_count = 0;   // reset for next graph replay
            }
        }
    }
}

extern "C" void kernel_launch(void* const* d_in, const int* in_sizes, int n_in,
                              void* d_out, int out_size)
{
    const float* x  = (const float*)d_in[0];
    const float* a  = (const float*)d_in[1];
    const float* b  = (const float*)d_in[2];
    const float* mu = (const float*)d_in[3];
    float* out = (float*)d_out;

    rosen_fused_kernel<<<GBLOCKS, THREADS>>>(x, a, b, mu, out);
}